// round 14
// baseline (speedup 1.0000x reference)
#include <cuda_runtime.h>
#include <cuda_fp16.h>

#define G   16
#define Bsz 2
#define C   256
#define Cg  16
#define HW  576
#define AC  6400
#define EPSV 1e-5f

// -------- device scratch --------
__device__ float g_h1[G * Bsz * C * HW];   // 18.9 MB (consumed by k4)
__device__ float g_pooled[G * Bsz * AC];
__device__ float g_aff[G * Bsz * G];

// ---------- fp16 helpers ----------
__device__ __forceinline__ unsigned int f2h2(float lo, float hi) {
    __half2 h = __floats2half2_rn(lo, hi);
    return *reinterpret_cast<unsigned int*>(&h);
}
__device__ __forceinline__ void mma_f16(
    float& d0, float& d1, float& d2, float& d3,
    unsigned int a0, unsigned int a1, unsigned int a2, unsigned int a3,
    unsigned int b0, unsigned int b1)
{
    asm("mma.sync.aligned.m16n8k16.row.col.f32.f16.f16.f32 "
        "{%0,%1,%2,%3}, {%4,%5,%6,%7}, {%8,%9}, {%0,%1,%2,%3};"
        : "+f"(d0), "+f"(d1), "+f"(d2), "+f"(d3)
        : "r"(a0), "r"(a1), "r"(a2), "r"(a3), "r"(b0), "r"(b1));
}

// ============================================================
// Fused kernel: conv3x3+BN+ReLU (phase A) -> smem fp16 tile ->
// 1x1 conv GEMM + BN + ReLU + avg-pool (phase B).
// grid (k=16, b=2, g=16), 416 threads = 13 warps.
//
// Phase A: warps 0-8 run the implicit-GEMM conv (72 n-tiles of 8 pos),
// write h1 fp32 to gmem (k4 needs it) AND the fp16 B tile for phase B
// directly into smem with channel pairing (q, q+8) — the pairing the
// conv epilogue produces naturally. hsum comes from the same registers.
//
// Phase B: all 13 warps; GEMM over the 16 channels with the K-order
// permuted to match the (q, q+8) pairing (A fragments index W2
// accordingly; sum over K is order-invariant). Epilogue = relu
// identity with exact linear part from hsum.
// ============================================================
#define BPITCH 680
// words: Bx 5440 | Aw 1152 | scb 32 | Hv 8*584=4672 | hpart 144 | hsum 16
#define FUSED_DYN ((5440 + 1152 + 32 + 4672 + 144 + 16) * 4)

__global__ __launch_bounds__(416) void k12_fused(
    const float* __restrict__ x,
    const float* __restrict__ W1,
    const float* __restrict__ g1, const float* __restrict__ b1,
    const float* __restrict__ m1, const float* __restrict__ v1,
    const float* __restrict__ W2,
    const float* __restrict__ g2, const float* __restrict__ b2,
    const float* __restrict__ m2, const float* __restrict__ v2)
{
    const int k = blockIdx.x, b = blockIdx.y, g = blockIdx.z;
    extern __shared__ unsigned int dyn[];
    unsigned int* Bx   = dyn;                    // x tile, 8 ci-pairs x BPITCH
    unsigned int* Aw   = Bx + 5440;              // conv A taps [tap9][pair8][row16]
    float*        scb  = reinterpret_cast<float*>(Aw + 1152);
    unsigned int* Hv   = Aw + 1152 + 32;         // h tile fp16x2, pair (q, q+8), pitch 584
    float*        hpart= reinterpret_cast<float*>(Hv + 4672);  // [16][9]
    float*        hsum = hpart + 144;

    const int tid = threadIdx.x;

    // ---------------- Phase A: conv ----------------
    for (int i = tid; i < 8 * BPITCH; i += 416) Bx[i] = 0u;

    const float* wsrc = W1 + (g * 256 + k * 16) * 144;  // [co16][ci16][tap9]
    for (int i = tid; i < 1152; i += 416) {
        int t = i / 128, rem = i % 128, p = rem / 16, r = rem % 16;
        Aw[i] = f2h2(wsrc[r * 144 + (2 * p) * 9 + t],
                     wsrc[r * 144 + (2 * p + 1) * 9 + t]);
    }
    if (tid < 16) {
        const int ch = g * 256 + k * 16 + tid;
        float sc = g1[ch] * rsqrtf(v1[ch] + EPSV);
        scb[tid] = sc;
        scb[16 + tid] = b1[ch] - m1[ch] * sc;
    }
    __syncthreads();

    const float* xs = x + (b * 256 + k * 16) * 576;
    for (int i = tid; i < 8 * 576; i += 416) {
        int q = i / 576, pos = i % 576;
        int y = pos / 24, xx = pos % 24;
        Bx[q * BPITCH + (y + 1) * 26 + (xx + 1)] =
            f2h2(xs[(2 * q) * 576 + pos], xs[(2 * q + 1) * 576 + pos]);
    }
    __syncthreads();

    const int w    = tid >> 5;
    const int lane = tid & 31;
    const int gq   = lane >> 2;
    const int tg   = lane & 3;

    if (w < 9) {
        float d[8][4];
#pragma unroll
        for (int j = 0; j < 8; ++j)
#pragma unroll
            for (int c = 0; c < 4; ++c) d[j][c] = 0.f;

#pragma unroll
        for (int t = 0; t < 9; ++t) {
            const int base = t * 128;
            unsigned int a0 = Aw[base + tg * 16 + gq];
            unsigned int a1 = Aw[base + tg * 16 + gq + 8];
            unsigned int a2 = Aw[base + (tg + 4) * 16 + gq];
            unsigned int a3 = Aw[base + (tg + 4) * 16 + gq + 8];
            const int ty = t / 3, tx = t % 3;
#pragma unroll
            for (int j = 0; j < 8; ++j) {
                const int nt = w * 8 + j;
                const int y = nt / 3, x0 = (nt % 3) * 8;
                const int pp = (y + ty) * 26 + x0 + gq + tx;
                unsigned int b0 = Bx[tg * BPITCH + pp];
                unsigned int b1v = Bx[(tg + 4) * BPITCH + pp];
                mma_f16(d[j][0], d[j][1], d[j][2], d[j][3], a0, a1, a2, a3, b0, b1v);
            }
        }

        // epilogue: BN+ReLU -> gmem fp32 h1, smem fp16 Hv (pair gq,gq+8), hsum partials
        const float sc0 = scb[gq],     bi0 = scb[16 + gq];
        const float sc1 = scb[gq + 8], bi1 = scb[24 + gq];
        float* dst = g_h1 + ((g * 2 + b) * 256 + k * 16) * 576;
        float rs0 = 0.f, rs1 = 0.f;
#pragma unroll
        for (int j = 0; j < 8; ++j) {
            const int nt = w * 8 + j;
            const int pos = nt * 8 + 2 * tg;
            float2 v0, v1;
            v0.x = fmaxf(fmaf(d[j][0], sc0, bi0), 0.f);
            v0.y = fmaxf(fmaf(d[j][1], sc0, bi0), 0.f);
            v1.x = fmaxf(fmaf(d[j][2], sc1, bi1), 0.f);
            v1.y = fmaxf(fmaf(d[j][3], sc1, bi1), 0.f);
            *reinterpret_cast<float2*>(dst + gq * 576 + pos)       = v0;
            *reinterpret_cast<float2*>(dst + (gq + 8) * 576 + pos) = v1;
            // paired fp16 tile: Hv[gq][pos] = (row gq, row gq+8)
            unsigned long long pk =
                (unsigned long long)f2h2(v0.x, v1.x) |
                ((unsigned long long)f2h2(v0.y, v1.y) << 32);
            *reinterpret_cast<unsigned long long*>(&Hv[gq * 584 + pos]) = pk;
            rs0 += v0.x + v0.y;
            rs1 += v1.x + v1.y;
        }
        rs0 += __shfl_xor_sync(0xffffffffu, rs0, 1);
        rs0 += __shfl_xor_sync(0xffffffffu, rs0, 2);
        rs1 += __shfl_xor_sync(0xffffffffu, rs1, 1);
        rs1 += __shfl_xor_sync(0xffffffffu, rs1, 2);
        if (tg == 0) {
            hpart[gq * 9 + w]       = rs0;
            hpart[(gq + 8) * 9 + w] = rs1;
        }
    }
    __syncthreads();
    if (tid < 16) {
        float s = 0.f;
#pragma unroll
        for (int j = 0; j < 9; ++j) s += hpart[tid * 9 + j];
        hsum[tid] = s;
    }
    __syncthreads();

    // ---------------- Phase B: 1x1 GEMM + pool ----------------
    const int s0i = w;
    const int s1raw = w + 13;
    const int s1i = (s1raw < 25) ? s1raw : s0i;   // warp 12 duplicates (benign)

    // hsum values for this thread's permuted K slots
    const float hsA = hsum[tg];
    const float hsB = hsum[tg + 8];
    const float hsC = hsum[tg + 4];
    const float hsD = hsum[tg + 12];

    unsigned int ah[2][4];
    float sc[2][2], bi[2][2], bip[2][2], Sd[2][2];
    int acB[2];
    const int ss[2] = { s0i, s1i };
#pragma unroll
    for (int e = 0; e < 2; ++e) {
        acB[e] = k * 400 + ss[e] * 16;
        const int pi0 = g * 6400 + acB[e] + gq;
        const int pi1 = pi0 + 8;
        const float* R0 = W2 + (size_t)pi0 * 16;
        const float* R1 = W2 + (size_t)pi1 * 16;
        // permuted K: slots (2tg,2tg+1) = channels (tg, tg+8);
        //             slots (2tg+8,2tg+9) = channels (tg+4, tg+12)
        float r0a = R0[tg], r0b = R0[tg + 8], r0c = R0[tg + 4], r0d = R0[tg + 12];
        float r1a = R1[tg], r1b = R1[tg + 8], r1c = R1[tg + 4], r1d = R1[tg + 12];
        ah[e][0] = f2h2(r0a, r0b);
        ah[e][1] = f2h2(r1a, r1b);
        ah[e][2] = f2h2(r0c, r0d);
        ah[e][3] = f2h2(r1c, r1d);
        sc[e][0] = g2[pi0] * rsqrtf(v2[pi0] + EPSV);
        bi[e][0] = b2[pi0] - m2[pi0] * sc[e][0];
        sc[e][1] = g2[pi1] * rsqrtf(v2[pi1] + EPSV);
        bi[e][1] = b2[pi1] - m2[pi1] * sc[e][1];
        bip[e][0] = bi[e][0] / sc[e][0];
        bip[e][1] = bi[e][1] / sc[e][1];
        Sd[e][0] = r0a * hsA + r0b * hsB + r0c * hsC + r0d * hsD;
        Sd[e][1] = r1a * hsA + r1b * hsB + r1c * hsC + r1d * hsD;
    }

    float T[2][2] = {{0.f, 0.f}, {0.f, 0.f}};   // Sum |d + bi/sc|

#pragma unroll 4
    for (int nt = 0; nt < 72; ++nt) {
        const int pos = nt * 8 + gq;
        unsigned int b0 = Hv[tg * 584 + pos];
        unsigned int b1v = Hv[(tg + 4) * 584 + pos];

#pragma unroll
        for (int e = 0; e < 2; ++e) {
            float d0 = 0.f, d1 = 0.f, d2 = 0.f, d3 = 0.f;
            mma_f16(d0, d1, d2, d3, ah[e][0], ah[e][1], ah[e][2], ah[e][3], b0, b1v);
            T[e][0] += fabsf(d0 + bip[e][0]) + fabsf(d1 + bip[e][0]);
            T[e][1] += fabsf(d2 + bip[e][1]) + fabsf(d3 + bip[e][1]);
        }
    }

#pragma unroll
    for (int e = 0; e < 2; ++e) {
        float t0 = T[e][0], t1 = T[e][1];
        float s0 = Sd[e][0], s1 = Sd[e][1];
        t0 += __shfl_xor_sync(0xffffffffu, t0, 1);
        t0 += __shfl_xor_sync(0xffffffffu, t0, 2);
        t1 += __shfl_xor_sync(0xffffffffu, t1, 1);
        t1 += __shfl_xor_sync(0xffffffffu, t1, 2);
        s0 += __shfl_xor_sync(0xffffffffu, s0, 1);
        s0 += __shfl_xor_sync(0xffffffffu, s0, 2);
        s1 += __shfl_xor_sync(0xffffffffu, s1, 1);
        s1 += __shfl_xor_sync(0xffffffffu, s1, 2);
        if (tg == 0) {
            float* dst = g_pooled + (g * 2 + b) * 6400;
            float S0 = fmaf(sc[e][0], s0, 576.f * bi[e][0]);
            float R0 = 0.5f * fmaf(sc[e][0], t0, S0);
            float S1 = fmaf(sc[e][1], s1, 576.f * bi[e][1]);
            float R1 = 0.5f * fmaf(sc[e][1], t1, S1);
            dst[acB[e] + gq]     = (R0 + 100.f * fmaxf(bi[e][0], 0.f)) * (1.f / 676.f);
            dst[acB[e] + gq + 8] = (R1 + 100.f * fmaxf(bi[e][1], 0.f)) * (1.f / 676.f);
        }
    }
}

// ============================================================
// Kernel 3: affinity rows. grid 32 = (i*2+b), 512 thr = 16 warps
// ============================================================
__global__ __launch_bounds__(512) void k3_aff()
{
    const int ib = blockIdx.x;
    const int i = ib >> 1;
    const int wrp = threadIdx.x >> 5, lane = threadIdx.x & 31;
    const float* base = g_pooled + ib * 6400;
    const float* pa = base + i * 400;
    const float* pb = base + wrp * 400;
    float s = 0.f;
    for (int m = lane; m < 400; m += 32) s += pa[m] * pb[m];
#pragma unroll
    for (int o = 16; o; o >>= 1) s += __shfl_xor_sync(0xffffffffu, s, o);
    if (lane == 0) g_aff[ib * 16 + wrp] = s * (1.f / 16.f);
}

// ============================================================
// Kernel 4: z = aff . h1 -> out, float2 per thread (288 threads)
// grid (cg=16, q=2, i=16)
// ============================================================
__global__ __launch_bounds__(288) void k4_out(float* __restrict__ out)
{
    const int cg = blockIdx.x, q = blockIdx.y, i = blockIdx.z;
    __shared__ float a0[16], a1[16];
    const int tid = threadIdx.x;
    if (tid < 16)      a0[tid]      = g_aff[(i * 2 + 0) * 16 + tid];
    else if (tid < 32) a1[tid - 16] = g_aff[(i * 2 + 1) * 16 + (tid - 16)];
    __syncthreads();

    const float2* hb = reinterpret_cast<const float2*>(
        g_h1 + ((i * 2 + q) * 256 + cg) * 576) + tid;
    float2 acc0 = {0.f, 0.f};
    float2 acc1 = {0.f, 0.f};
#pragma unroll
    for (int kk = 0; kk < 16; ++kk) {
        float2 hv = hb[kk * 16 * 288];
        float w0 = a0[kk], w1 = a1[kk];
        acc0.x = fmaf(w0, hv.x, acc0.x); acc0.y = fmaf(w0, hv.y, acc0.y);
        acc1.x = fmaf(w1, hv.x, acc1.x); acc1.y = fmaf(w1, hv.y, acc1.y);
    }
    const int ch = (i * 2 + q) * 16 + cg;
    float2* o0 = reinterpret_cast<float2*>(out + (0 * 512 + ch) * 576) + tid;
    float2* o1 = reinterpret_cast<float2*>(out + (1 * 512 + ch) * 576) + tid;
    *o0 = acc0;
    *o1 = acc1;
}

// ============================================================
extern "C" void kernel_launch(void* const* d_in, const int* in_sizes, int n_in,
                              void* d_out, int out_size)
{
    const float* x  = (const float*)d_in[0];
    const float* W1 = (const float*)d_in[1];
    const float* g1 = (const float*)d_in[2];
    const float* b1 = (const float*)d_in[3];
    const float* m1 = (const float*)d_in[4];
    const float* v1 = (const float*)d_in[5];
    const float* W2 = (const float*)d_in[6];
    const float* g2 = (const float*)d_in[7];
    const float* b2 = (const float*)d_in[8];
    const float* m2 = (const float*)d_in[9];
    const float* v2 = (const float*)d_in[10];
    float* out = (float*)d_out;

    cudaFuncSetAttribute(k12_fused, cudaFuncAttributeMaxDynamicSharedMemorySize, FUSED_DYN);

    dim3 grid(16, 2, 16);
    k12_fused<<<grid, 416, FUSED_DYN>>>(x, W1, g1, b1, m1, v1,
                                        W2, g2, b2, m2, v2);
    k3_aff<<<32, 512>>>();
    k4_out<<<grid, 288>>>(out);
}

// round 15
// speedup vs baseline: 1.1944x; 1.1944x over previous
#include <cuda_runtime.h>
#include <cuda_fp16.h>

#define G   16
#define Bsz 2
#define C   256
#define Cg  16
#define HW  576
#define AC  6400
#define EPSV 1e-5f

// -------- device scratch --------
__device__ float g_h1[G * Bsz * C * HW];   // 18.9 MB
__device__ float g_pooled[G * Bsz * AC];
__device__ float g_aff[G * Bsz * G];

// ---------- fp16 helpers ----------
__device__ __forceinline__ unsigned int f2h2(float lo, float hi) {
    __half2 h = __floats2half2_rn(lo, hi);
    return *reinterpret_cast<unsigned int*>(&h);
}
__device__ __forceinline__ void mma_f16(
    float& d0, float& d1, float& d2, float& d3,
    unsigned int a0, unsigned int a1, unsigned int a2, unsigned int a3,
    unsigned int b0, unsigned int b1)
{
    asm("mma.sync.aligned.m16n8k16.row.col.f32.f16.f16.f32 "
        "{%0,%1,%2,%3}, {%4,%5,%6,%7}, {%8,%9}, {%0,%1,%2,%3};"
        : "+f"(d0), "+f"(d1), "+f"(d2), "+f"(d3)
        : "r"(a0), "r"(a1), "r"(a2), "r"(a3), "r"(b0), "r"(b1));
}

// ============================================================
// Kernel 1 (tensor cores): grouped 3x3 conv + BN + ReLU -> g_h1
// Implicit GEMM over K = 9 taps x 16 ci, single fp16.
// grid (k=16, b=2, g=16), 288 threads = 9 warps, 2 blocks/SM target.
// ============================================================
#define BPITCH 680
#define K1_DYN ((8*BPITCH + 9*128 + 32) * 4)

__global__ __launch_bounds__(288, 2) void k1_tc(
    const float* __restrict__ x,
    const float* __restrict__ W1,
    const float* __restrict__ g1, const float* __restrict__ b1,
    const float* __restrict__ m1, const float* __restrict__ v1)
{
    const int k = blockIdx.x, b = blockIdx.y, g = blockIdx.z;
    extern __shared__ unsigned int dyn[];
    unsigned int* Bv = dyn;                 // 8 ci-pairs x BPITCH (fp16x2)
    unsigned int* Ah = Bv + 8 * BPITCH;     // [tap9][pair8][row16]
    float* scb = reinterpret_cast<float*>(Ah + 9 * 128);

    const int tid = threadIdx.x;

    for (int i = tid; i < 8 * BPITCH; i += 288) Bv[i] = 0u;

    const float* wsrc = W1 + (g * 256 + k * 16) * 144;  // [co16][ci16][tap9]
    for (int i = tid; i < 1152; i += 288) {
        int t = i / 128, rem = i % 128, p = rem / 16, r = rem % 16;
        Ah[i] = f2h2(wsrc[r * 144 + (2 * p) * 9 + t],
                     wsrc[r * 144 + (2 * p + 1) * 9 + t]);
    }
    if (tid < 16) {
        const int ch = g * 256 + k * 16 + tid;
        float sc = g1[ch] * rsqrtf(v1[ch] + EPSV);
        scb[tid] = sc;
        scb[16 + tid] = b1[ch] - m1[ch] * sc;
    }
    __syncthreads();

    const float* xs = x + (b * 256 + k * 16) * 576;
    for (int i = tid; i < 8 * 576; i += 288) {
        int q = i / 576, pos = i % 576;
        int y = pos / 24, xx = pos % 24;
        Bv[q * BPITCH + (y + 1) * 26 + (xx + 1)] =
            f2h2(xs[(2 * q) * 576 + pos], xs[(2 * q + 1) * 576 + pos]);
    }
    __syncthreads();

    const int w    = tid >> 5;
    const int lane = tid & 31;
    const int gq   = lane >> 2;
    const int tg   = lane & 3;

    float d[8][4];
#pragma unroll
    for (int j = 0; j < 8; ++j)
#pragma unroll
        for (int c = 0; c < 4; ++c) d[j][c] = 0.f;

#pragma unroll
    for (int t = 0; t < 9; ++t) {
        const int base = t * 128;
        unsigned int ah0 = Ah[base + tg * 16 + gq];
        unsigned int ah1 = Ah[base + tg * 16 + gq + 8];
        unsigned int ah2 = Ah[base + (tg + 4) * 16 + gq];
        unsigned int ah3 = Ah[base + (tg + 4) * 16 + gq + 8];
        const int ty = t / 3, tx = t % 3;

#pragma unroll
        for (int j = 0; j < 8; ++j) {
            const int nt = w * 8 + j;
            const int y = nt / 3, x0 = (nt % 3) * 8;
            const int pp = (y + ty) * 26 + x0 + gq + tx;
            unsigned int b0 = Bv[tg * BPITCH + pp];
            unsigned int b1 = Bv[(tg + 4) * BPITCH + pp];
            mma_f16(d[j][0], d[j][1], d[j][2], d[j][3], ah0, ah1, ah2, ah3, b0, b1);
        }
    }

    const float sc0 = scb[gq],     bi0 = scb[16 + gq];
    const float sc1 = scb[gq + 8], bi1 = scb[24 + gq];
    float* dst = g_h1 + ((g * 2 + b) * 256 + k * 16) * 576;
#pragma unroll
    for (int j = 0; j < 8; ++j) {
        const int nt = w * 8 + j;
        const int pos = nt * 8 + 2 * tg;
        float2 v0, v1;
        v0.x = fmaxf(fmaf(d[j][0], sc0, bi0), 0.f);
        v0.y = fmaxf(fmaf(d[j][1], sc0, bi0), 0.f);
        v1.x = fmaxf(fmaf(d[j][2], sc1, bi1), 0.f);
        v1.y = fmaxf(fmaf(d[j][3], sc1, bi1), 0.f);
        *reinterpret_cast<float2*>(dst + gq * 576 + pos)       = v0;
        *reinterpret_cast<float2*>(dst + (gq + 8) * 576 + pos) = v1;
    }
}

// ============================================================
// Kernel 2 (tensor cores): per (g,b,k) GEMM + BN + ReLU + avg-pool.
// Single fp16 A and B. Epilogue: relu identity, exact linear part
// from hsum. 13 warps; warp w processes strips w and w+13 together.
// 2 blocks/SM target (reg cap 78).
// ============================================================
__global__ __launch_bounds__(416, 2) void k2_tc(
    const float* __restrict__ W2,
    const float* __restrict__ g2, const float* __restrict__ b2,
    const float* __restrict__ m2, const float* __restrict__ v2)
{
    const int k = blockIdx.x, b = blockIdx.y, g = blockIdx.z;

    __shared__ unsigned int Bv[8][584];   // pitch 584 (mod 32 == 8)
    __shared__ float part[16][48];
    __shared__ float hsum[16];

    const int tid = threadIdx.x;
    const float* src = g_h1 + ((g * 2 + b) * 256 + k * 16) * 576;

    if (tid < 384) {
        const int q = tid / 48, r = tid % 48;
        const float* s0p = src + (2 * q) * 576;
        const float* s1p = src + (2 * q + 1) * 576;
        float a0 = 0.f, a1 = 0.f;
#pragma unroll
        for (int n = 0; n < 12; ++n) {
            const int pos = r + 48 * n;
            float f0 = s0p[pos], f1 = s1p[pos];
            Bv[q][pos] = f2h2(f0, f1);
            a0 += f0; a1 += f1;
        }
        part[2 * q][r] = a0;
        part[2 * q + 1][r] = a1;
    }
    __syncthreads();
    if (tid < 16) {
        float s = 0.f;
#pragma unroll
        for (int j = 0; j < 48; ++j) s += part[tid][j];
        hsum[tid] = s;
    }
    __syncthreads();

    const int w    = tid >> 5;
    const int lane = tid & 31;
    const int gq   = lane >> 2;
    const int tg   = lane & 3;

    const int s0i = w;
    const int s1raw = w + 13;
    const int s1i = (s1raw < 25) ? s1raw : s0i;   // warp 12 duplicates (benign)

    const float hs0 = hsum[2 * tg];
    const float hs1 = hsum[2 * tg + 1];
    const float hs2 = hsum[2 * tg + 8];
    const float hs3 = hsum[2 * tg + 9];

    unsigned int ah[2][4];
    float sc[2][2], bi[2][2], bip[2][2], Sd[2][2];
    int acB[2];
    const int ss[2] = { s0i, s1i };
#pragma unroll
    for (int e = 0; e < 2; ++e) {
        acB[e] = k * 400 + ss[e] * 16;
        const int pi0 = g * 6400 + acB[e] + gq;
        const int pi1 = pi0 + 8;
        const float2* A0 = reinterpret_cast<const float2*>(W2 + (size_t)pi0 * 16);
        const float2* A1 = reinterpret_cast<const float2*>(W2 + (size_t)pi1 * 16);
        float2 p00 = A0[tg], p02 = A0[tg + 4];
        float2 p10 = A1[tg], p12 = A1[tg + 4];
        ah[e][0] = f2h2(p00.x, p00.y);
        ah[e][1] = f2h2(p10.x, p10.y);
        ah[e][2] = f2h2(p02.x, p02.y);
        ah[e][3] = f2h2(p12.x, p12.y);
        sc[e][0] = g2[pi0] * rsqrtf(v2[pi0] + EPSV);
        bi[e][0] = b2[pi0] - m2[pi0] * sc[e][0];
        sc[e][1] = g2[pi1] * rsqrtf(v2[pi1] + EPSV);
        bi[e][1] = b2[pi1] - m2[pi1] * sc[e][1];
        bip[e][0] = bi[e][0] / sc[e][0];
        bip[e][1] = bi[e][1] / sc[e][1];
        Sd[e][0] = p00.x * hs0 + p00.y * hs1 + p02.x * hs2 + p02.y * hs3;
        Sd[e][1] = p10.x * hs0 + p10.y * hs1 + p12.x * hs2 + p12.y * hs3;
    }

    float T[2][2] = {{0.f, 0.f}, {0.f, 0.f}};   // Sum |d + bi/sc|

#pragma unroll 4
    for (int nt = 0; nt < 72; ++nt) {
        const int pos = nt * 8 + gq;
        unsigned int b0 = Bv[tg][pos];
        unsigned int b1 = Bv[tg + 4][pos];

#pragma unroll
        for (int e = 0; e < 2; ++e) {
            float d0 = 0.f, d1 = 0.f, d2 = 0.f, d3 = 0.f;
            mma_f16(d0, d1, d2, d3, ah[e][0], ah[e][1], ah[e][2], ah[e][3], b0, b1);
            T[e][0] += fabsf(d0 + bip[e][0]) + fabsf(d1 + bip[e][0]);
            T[e][1] += fabsf(d2 + bip[e][1]) + fabsf(d3 + bip[e][1]);
        }
    }

#pragma unroll
    for (int e = 0; e < 2; ++e) {
        float t0 = T[e][0], t1 = T[e][1];
        float s0 = Sd[e][0], s1 = Sd[e][1];
        t0 += __shfl_xor_sync(0xffffffffu, t0, 1);
        t0 += __shfl_xor_sync(0xffffffffu, t0, 2);
        t1 += __shfl_xor_sync(0xffffffffu, t1, 1);
        t1 += __shfl_xor_sync(0xffffffffu, t1, 2);
        s0 += __shfl_xor_sync(0xffffffffu, s0, 1);
        s0 += __shfl_xor_sync(0xffffffffu, s0, 2);
        s1 += __shfl_xor_sync(0xffffffffu, s1, 1);
        s1 += __shfl_xor_sync(0xffffffffu, s1, 2);
        if (tg == 0) {
            float* dst = g_pooled + (g * 2 + b) * 6400;
            float S0 = fmaf(sc[e][0], s0, 576.f * bi[e][0]);
            float R0 = 0.5f * fmaf(sc[e][0], t0, S0);
            float S1 = fmaf(sc[e][1], s1, 576.f * bi[e][1]);
            float R1 = 0.5f * fmaf(sc[e][1], t1, S1);
            dst[acB[e] + gq]     = (R0 + 100.f * fmaxf(bi[e][0], 0.f)) * (1.f / 676.f);
            dst[acB[e] + gq + 8] = (R1 + 100.f * fmaxf(bi[e][1], 0.f)) * (1.f / 676.f);
        }
    }
}

// ============================================================
// Kernel 3: affinity rows. grid 32 = (i*2+b), 512 thr = 16 warps
// ============================================================
__global__ __launch_bounds__(512) void k3_aff()
{
    const int ib = blockIdx.x;
    const int i = ib >> 1;
    const int wrp = threadIdx.x >> 5, lane = threadIdx.x & 31;
    const float* base = g_pooled + ib * 6400;
    const float* pa = base + i * 400;
    const float* pb = base + wrp * 400;
    float s = 0.f;
    for (int m = lane; m < 400; m += 32) s += pa[m] * pb[m];
#pragma unroll
    for (int o = 16; o; o >>= 1) s += __shfl_xor_sync(0xffffffffu, s, o);
    if (lane == 0) g_aff[ib * 16 + wrp] = s * (1.f / 16.f);
}

// ============================================================
// Kernel 4: z = aff . h1 -> out, float2 per thread (288 threads)
// grid (cg=16, q=2, i=16)
// ============================================================
__global__ __launch_bounds__(288) void k4_out(float* __restrict__ out)
{
    const int cg = blockIdx.x, q = blockIdx.y, i = blockIdx.z;
    __shared__ float a0[16], a1[16];
    const int tid = threadIdx.x;
    if (tid < 16)      a0[tid]      = g_aff[(i * 2 + 0) * 16 + tid];
    else if (tid < 32) a1[tid - 16] = g_aff[(i * 2 + 1) * 16 + (tid - 16)];
    __syncthreads();

    const float2* hb = reinterpret_cast<const float2*>(
        g_h1 + ((i * 2 + q) * 256 + cg) * 576) + tid;
    float2 acc0 = {0.f, 0.f};
    float2 acc1 = {0.f, 0.f};
#pragma unroll
    for (int kk = 0; kk < 16; ++kk) {
        float2 hv = hb[kk * 16 * 288];
        float w0 = a0[kk], w1 = a1[kk];
        acc0.x = fmaf(w0, hv.x, acc0.x); acc0.y = fmaf(w0, hv.y, acc0.y);
        acc1.x = fmaf(w1, hv.x, acc1.x); acc1.y = fmaf(w1, hv.y, acc1.y);
    }
    const int ch = (i * 2 + q) * 16 + cg;
    float2* o0 = reinterpret_cast<float2*>(out + (0 * 512 + ch) * 576) + tid;
    float2* o1 = reinterpret_cast<float2*>(out + (1 * 512 + ch) * 576) + tid;
    *o0 = acc0;
    *o1 = acc1;
}

// ============================================================
extern "C" void kernel_launch(void* const* d_in, const int* in_sizes, int n_in,
                              void* d_out, int out_size)
{
    const float* x  = (const float*)d_in[0];
    const float* W1 = (const float*)d_in[1];
    const float* g1 = (const float*)d_in[2];
    const float* b1 = (const float*)d_in[3];
    const float* m1 = (const float*)d_in[4];
    const float* v1 = (const float*)d_in[5];
    const float* W2 = (const float*)d_in[6];
    const float* g2 = (const float*)d_in[7];
    const float* b2 = (const float*)d_in[8];
    const float* m2 = (const float*)d_in[9];
    const float* v2 = (const float*)d_in[10];
    float* out = (float*)d_out;

    cudaFuncSetAttribute(k1_tc, cudaFuncAttributeMaxDynamicSharedMemorySize, K1_DYN);

    dim3 grid(16, 2, 16);
    k1_tc <<<grid, 288, K1_DYN>>>(x, W1, g1, b1, m1, v1);
    k2_tc <<<grid, 416>>>(W2, g2, b2, m2, v2);
    k3_aff<<<32, 512>>>();
    k4_out<<<grid, 288>>>(out);
}

// round 16
// speedup vs baseline: 1.2476x; 1.0445x over previous
#include <cuda_runtime.h>
#include <cuda_fp16.h>

#define G   16
#define Bsz 2
#define C   256
#define Cg  16
#define HW  576
#define AC  6400
#define EPSV 1e-5f

// -------- device scratch --------
// h1 stored as fp16x2 words: tile t=(g*2+b)*16+k, row q (0..7), pos (0..575);
// word = (half lo = ch k*16+q, half hi = ch k*16+q+8)
__device__ unsigned int g_h1p[512 * 8 * 576];   // 9.4 MB
__device__ float g_pooled[G * Bsz * AC];
__device__ float g_aff[G * Bsz * G];

// ---------- fp16 helpers ----------
__device__ __forceinline__ unsigned int f2h2(float lo, float hi) {
    __half2 h = __floats2half2_rn(lo, hi);
    return *reinterpret_cast<unsigned int*>(&h);
}
__device__ __forceinline__ void mma_f16(
    float& d0, float& d1, float& d2, float& d3,
    unsigned int a0, unsigned int a1, unsigned int a2, unsigned int a3,
    unsigned int b0, unsigned int b1)
{
    asm("mma.sync.aligned.m16n8k16.row.col.f32.f16.f16.f32 "
        "{%0,%1,%2,%3}, {%4,%5,%6,%7}, {%8,%9}, {%0,%1,%2,%3};"
        : "+f"(d0), "+f"(d1), "+f"(d2), "+f"(d3)
        : "r"(a0), "r"(a1), "r"(a2), "r"(a3), "r"(b0), "r"(b1));
}

// ============================================================
// Kernel 1 (tensor cores): grouped 3x3 conv + BN + ReLU -> g_h1p (fp16x2)
// Implicit GEMM over K = 9 taps x 16 ci, single fp16.
// grid (k=16, b=2, g=16), 288 threads = 9 warps.
// ============================================================
#define BPITCH 680
#define K1_DYN ((8*BPITCH + 9*128 + 32) * 4)

__global__ __launch_bounds__(288, 2) void k1_tc(
    const float* __restrict__ x,
    const float* __restrict__ W1,
    const float* __restrict__ g1, const float* __restrict__ b1,
    const float* __restrict__ m1, const float* __restrict__ v1)
{
    const int k = blockIdx.x, b = blockIdx.y, g = blockIdx.z;
    extern __shared__ unsigned int dyn[];
    unsigned int* Bv = dyn;                 // 8 ci-pairs x BPITCH (fp16x2)
    unsigned int* Ah = Bv + 8 * BPITCH;     // [tap9][pair8][row16]
    float* scb = reinterpret_cast<float*>(Ah + 9 * 128);

    const int tid = threadIdx.x;

    for (int i = tid; i < 8 * BPITCH; i += 288) Bv[i] = 0u;

    const float* wsrc = W1 + (g * 256 + k * 16) * 144;  // [co16][ci16][tap9]
    for (int i = tid; i < 1152; i += 288) {
        int t = i / 128, rem = i % 128, p = rem / 16, r = rem % 16;
        Ah[i] = f2h2(wsrc[r * 144 + (2 * p) * 9 + t],
                     wsrc[r * 144 + (2 * p + 1) * 9 + t]);
    }
    if (tid < 16) {
        const int ch = g * 256 + k * 16 + tid;
        float sc = g1[ch] * rsqrtf(v1[ch] + EPSV);
        scb[tid] = sc;
        scb[16 + tid] = b1[ch] - m1[ch] * sc;
    }
    __syncthreads();

    const float* xs = x + (b * 256 + k * 16) * 576;
    for (int i = tid; i < 8 * 576; i += 288) {
        int q = i / 576, pos = i % 576;
        int y = pos / 24, xx = pos % 24;
        Bv[q * BPITCH + (y + 1) * 26 + (xx + 1)] =
            f2h2(xs[(2 * q) * 576 + pos], xs[(2 * q + 1) * 576 + pos]);
    }
    __syncthreads();

    const int w    = tid >> 5;
    const int lane = tid & 31;
    const int gq   = lane >> 2;
    const int tg   = lane & 3;

    float d[8][4];
#pragma unroll
    for (int j = 0; j < 8; ++j)
#pragma unroll
        for (int c = 0; c < 4; ++c) d[j][c] = 0.f;

#pragma unroll
    for (int t = 0; t < 9; ++t) {
        const int base = t * 128;
        unsigned int ah0 = Ah[base + tg * 16 + gq];
        unsigned int ah1 = Ah[base + tg * 16 + gq + 8];
        unsigned int ah2 = Ah[base + (tg + 4) * 16 + gq];
        unsigned int ah3 = Ah[base + (tg + 4) * 16 + gq + 8];
        const int ty = t / 3, tx = t % 3;

#pragma unroll
        for (int j = 0; j < 8; ++j) {
            const int nt = w * 8 + j;
            const int y = nt / 3, x0 = (nt % 3) * 8;
            const int pp = (y + ty) * 26 + x0 + gq + tx;
            unsigned int b0 = Bv[tg * BPITCH + pp];
            unsigned int b1 = Bv[(tg + 4) * BPITCH + pp];
            mma_f16(d[j][0], d[j][1], d[j][2], d[j][3], ah0, ah1, ah2, ah3, b0, b1);
        }
    }

    // epilogue: BN + ReLU, pack rows (gq, gq+8) into fp16x2 words
    const float sc0 = scb[gq],     bi0 = scb[16 + gq];
    const float sc1 = scb[gq + 8], bi1 = scb[24 + gq];
    unsigned int* dstp = g_h1p + (((g * 2 + b) * 16 + k) * 8 + gq) * 576;
#pragma unroll
    for (int j = 0; j < 8; ++j) {
        const int nt = w * 8 + j;
        const int pos = nt * 8 + 2 * tg;
        float v0x = fmaxf(fmaf(d[j][0], sc0, bi0), 0.f);
        float v0y = fmaxf(fmaf(d[j][1], sc0, bi0), 0.f);
        float v1x = fmaxf(fmaf(d[j][2], sc1, bi1), 0.f);
        float v1y = fmaxf(fmaf(d[j][3], sc1, bi1), 0.f);
        uint2 pk;
        pk.x = f2h2(v0x, v1x);   // pos:   (row gq, row gq+8)
        pk.y = f2h2(v0y, v1y);   // pos+1
        *reinterpret_cast<uint2*>(dstp + pos) = pk;
    }
}

// ============================================================
// Kernel 2 (tensor cores): per (g,b,k) GEMM + BN + ReLU + avg-pool.
// B tile loaded as packed fp16x2 words (pairing (q, q+8)); A fragments
// use the matching permuted K-order. hsum computed from the same fp16
// values the MMA consumes. Epilogue: relu identity + exact linear part.
// ============================================================
__global__ __launch_bounds__(416, 2) void k2_tc(
    const float* __restrict__ W2,
    const float* __restrict__ g2, const float* __restrict__ b2,
    const float* __restrict__ m2, const float* __restrict__ v2)
{
    const int k = blockIdx.x, b = blockIdx.y, g = blockIdx.z;

    __shared__ unsigned int Bv[8][584];   // pitch 584 (mod 32 == 8)
    __shared__ float part[16][48];
    __shared__ float hsum[16];

    const int tid = threadIdx.x;
    const unsigned int* src = g_h1p + ((g * 2 + b) * 16 + k) * 4608;

    if (tid < 384) {
        const int q = tid / 48, r = tid % 48;
        const unsigned int* sp = src + q * 576;
        float a0 = 0.f, a1 = 0.f;
#pragma unroll
        for (int n = 0; n < 12; ++n) {
            const int pos = r + 48 * n;
            unsigned int wv = sp[pos];
            Bv[q][pos] = wv;
            float2 f = __half22float2(*reinterpret_cast<const __half2*>(&wv));
            a0 += f.x; a1 += f.y;
        }
        part[q][r]     = a0;   // channel q
        part[q + 8][r] = a1;   // channel q+8
    }
    __syncthreads();
    if (tid < 16) {
        float s = 0.f;
#pragma unroll
        for (int j = 0; j < 48; ++j) s += part[tid][j];
        hsum[tid] = s;
    }
    __syncthreads();

    const int w    = tid >> 5;
    const int lane = tid & 31;
    const int gq   = lane >> 2;
    const int tg   = lane & 3;

    const int s0i = w;
    const int s1raw = w + 13;
    const int s1i = (s1raw < 25) ? s1raw : s0i;   // warp 12 duplicates (benign)

    // hsum values for this thread's permuted K slots
    const float hsA = hsum[tg];
    const float hsB = hsum[tg + 8];
    const float hsC = hsum[tg + 4];
    const float hsD = hsum[tg + 12];

    unsigned int ah[2][4];
    float sc[2][2], bi[2][2], bip[2][2], Sd[2][2];
    int acB[2];
    const int ss[2] = { s0i, s1i };
#pragma unroll
    for (int e = 0; e < 2; ++e) {
        acB[e] = k * 400 + ss[e] * 16;
        const int pi0 = g * 6400 + acB[e] + gq;
        const int pi1 = pi0 + 8;
        const float* R0 = W2 + (size_t)pi0 * 16;
        const float* R1 = W2 + (size_t)pi1 * 16;
        // permuted K: slots (2tg,2tg+1) = channels (tg, tg+8);
        //             slots (2tg+8,2tg+9) = channels (tg+4, tg+12)
        float r0a = R0[tg], r0b = R0[tg + 8], r0c = R0[tg + 4], r0d = R0[tg + 12];
        float r1a = R1[tg], r1b = R1[tg + 8], r1c = R1[tg + 4], r1d = R1[tg + 12];
        ah[e][0] = f2h2(r0a, r0b);
        ah[e][1] = f2h2(r1a, r1b);
        ah[e][2] = f2h2(r0c, r0d);
        ah[e][3] = f2h2(r1c, r1d);
        sc[e][0] = g2[pi0] * rsqrtf(v2[pi0] + EPSV);
        bi[e][0] = b2[pi0] - m2[pi0] * sc[e][0];
        sc[e][1] = g2[pi1] * rsqrtf(v2[pi1] + EPSV);
        bi[e][1] = b2[pi1] - m2[pi1] * sc[e][1];
        bip[e][0] = bi[e][0] / sc[e][0];
        bip[e][1] = bi[e][1] / sc[e][1];
        Sd[e][0] = r0a * hsA + r0b * hsB + r0c * hsC + r0d * hsD;
        Sd[e][1] = r1a * hsA + r1b * hsB + r1c * hsC + r1d * hsD;
    }

    float T[2][2] = {{0.f, 0.f}, {0.f, 0.f}};   // Sum |d + bi/sc|

#pragma unroll 4
    for (int nt = 0; nt < 72; ++nt) {
        const int pos = nt * 8 + gq;
        unsigned int b0 = Bv[tg][pos];
        unsigned int b1 = Bv[tg + 4][pos];

#pragma unroll
        for (int e = 0; e < 2; ++e) {
            float d0 = 0.f, d1 = 0.f, d2 = 0.f, d3 = 0.f;
            mma_f16(d0, d1, d2, d3, ah[e][0], ah[e][1], ah[e][2], ah[e][3], b0, b1);
            T[e][0] += fabsf(d0 + bip[e][0]) + fabsf(d1 + bip[e][0]);
            T[e][1] += fabsf(d2 + bip[e][1]) + fabsf(d3 + bip[e][1]);
        }
    }

#pragma unroll
    for (int e = 0; e < 2; ++e) {
        float t0 = T[e][0], t1 = T[e][1];
        float s0 = Sd[e][0], s1 = Sd[e][1];
        t0 += __shfl_xor_sync(0xffffffffu, t0, 1);
        t0 += __shfl_xor_sync(0xffffffffu, t0, 2);
        t1 += __shfl_xor_sync(0xffffffffu, t1, 1);
        t1 += __shfl_xor_sync(0xffffffffu, t1, 2);
        s0 += __shfl_xor_sync(0xffffffffu, s0, 1);
        s0 += __shfl_xor_sync(0xffffffffu, s0, 2);
        s1 += __shfl_xor_sync(0xffffffffu, s1, 1);
        s1 += __shfl_xor_sync(0xffffffffu, s1, 2);
        if (tg == 0) {
            float* dst = g_pooled + (g * 2 + b) * 6400;
            float S0 = fmaf(sc[e][0], s0, 576.f * bi[e][0]);
            float R0 = 0.5f * fmaf(sc[e][0], t0, S0);
            float S1 = fmaf(sc[e][1], s1, 576.f * bi[e][1]);
            float R1 = 0.5f * fmaf(sc[e][1], t1, S1);
            dst[acB[e] + gq]     = (R0 + 100.f * fmaxf(bi[e][0], 0.f)) * (1.f / 676.f);
            dst[acB[e] + gq + 8] = (R1 + 100.f * fmaxf(bi[e][1], 0.f)) * (1.f / 676.f);
        }
    }
}

// ============================================================
// Kernel 3: affinity rows. grid 32 = (i*2+b), 512 thr = 16 warps
// ============================================================
__global__ __launch_bounds__(512) void k3_aff()
{
    const int ib = blockIdx.x;
    const int i = ib >> 1;
    const int wrp = threadIdx.x >> 5, lane = threadIdx.x & 31;
    const float* base = g_pooled + ib * 6400;
    const float* pa = base + i * 400;
    const float* pb = base + wrp * 400;
    float s = 0.f;
    for (int m = lane; m < 400; m += 32) s += pa[m] * pb[m];
#pragma unroll
    for (int o = 16; o; o >>= 1) s += __shfl_xor_sync(0xffffffffu, s, o);
    if (lane == 0) g_aff[ib * 16 + wrp] = s * (1.f / 16.f);
}

// ============================================================
// Kernel 4: z = aff . h1 -> out, reading packed fp16 pairs.
// grid (cgp=8, q=2, i=16) = 256 blocks, 288 threads; each thread owns
// 2 positions and produces 2 channels (cgp, cgp+8) x 2 batches.
// ============================================================
__global__ __launch_bounds__(288) void k4_out(float* __restrict__ out)
{
    const int cgp = blockIdx.x, q = blockIdx.y, i = blockIdx.z;
    __shared__ float a0[16], a1[16];
    const int tid = threadIdx.x;
    if (tid < 16)      a0[tid]      = g_aff[(i * 2 + 0) * 16 + tid];
    else if (tid < 32) a1[tid - 16] = g_aff[(i * 2 + 1) * 16 + (tid - 16)];
    __syncthreads();

    // word [tile (i*2+q)*16+kk][row cgp][pos]: (lo = ch kk*16+cgp, hi = +8)
    const uint2* hb = reinterpret_cast<const uint2*>(
        g_h1p + ((size_t)((i * 2 + q) * 16) * 8 + cgp) * 576) + tid;

    float2 lo0 = {0.f, 0.f}, hi0 = {0.f, 0.f};
    float2 lo1 = {0.f, 0.f}, hi1 = {0.f, 0.f};
#pragma unroll
    for (int kk = 0; kk < 16; ++kk) {
        uint2 wv = hb[kk * 2304];   // 4608 words per tile / 2 per uint2
        float2 f0 = __half22float2(*reinterpret_cast<const __half2*>(&wv.x)); // pos0
        float2 f1 = __half22float2(*reinterpret_cast<const __half2*>(&wv.y)); // pos1
        float w0 = a0[kk], w1 = a1[kk];
        lo0.x = fmaf(w0, f0.x, lo0.x); lo0.y = fmaf(w0, f1.x, lo0.y);
        hi0.x = fmaf(w0, f0.y, hi0.x); hi0.y = fmaf(w0, f1.y, hi0.y);
        lo1.x = fmaf(w1, f0.x, lo1.x); lo1.y = fmaf(w1, f1.x, lo1.y);
        hi1.x = fmaf(w1, f0.y, hi1.x); hi1.y = fmaf(w1, f1.y, hi1.y);
    }
    const int chLo = (i * 2 + q) * 16 + cgp;
    *(reinterpret_cast<float2*>(out + (0 * 512 + chLo)     * 576) + tid) = lo0;
    *(reinterpret_cast<float2*>(out + (0 * 512 + chLo + 8) * 576) + tid) = hi0;
    *(reinterpret_cast<float2*>(out + (1 * 512 + chLo)     * 576) + tid) = lo1;
    *(reinterpret_cast<float2*>(out + (1 * 512 + chLo + 8) * 576) + tid) = hi1;
}

// ============================================================
extern "C" void kernel_launch(void* const* d_in, const int* in_sizes, int n_in,
                              void* d_out, int out_size)
{
    const float* x  = (const float*)d_in[0];
    const float* W1 = (const float*)d_in[1];
    const float* g1 = (const float*)d_in[2];
    const float* b1 = (const float*)d_in[3];
    const float* m1 = (const float*)d_in[4];
    const float* v1 = (const float*)d_in[5];
    const float* W2 = (const float*)d_in[6];
    const float* g2 = (const float*)d_in[7];
    const float* b2 = (const float*)d_in[8];
    const float* m2 = (const float*)d_in[9];
    const float* v2 = (const float*)d_in[10];
    float* out = (float*)d_out;

    cudaFuncSetAttribute(k1_tc, cudaFuncAttributeMaxDynamicSharedMemorySize, K1_DYN);

    dim3 grid(16, 2, 16);
    dim3 grid4(8, 2, 16);
    k1_tc <<<grid, 288, K1_DYN>>>(x, W1, g1, b1, m1, v1);
    k2_tc <<<grid, 416>>>(W2, g2, b2, m2, v2);
    k3_aff<<<32, 512>>>();
    k4_out<<<grid4, 288>>>(out);
}

// round 17
// speedup vs baseline: 1.3513x; 1.0831x over previous
#include <cuda_runtime.h>
#include <cuda_fp16.h>

#define G   16
#define Bsz 2
#define C   256
#define Cg  16
#define HW  576
#define AC  6400
#define EPSV 1e-5f

// -------- device scratch --------
// h1 stored as fp16x2 words: tile t=(g*2+b)*16+k, row q (0..7), pos (0..575);
// word = (half lo = ch k*16+q, half hi = ch k*16+q+8)
__device__ unsigned int g_h1p[512 * 8 * 576];   // 9.4 MB
__device__ float g_pooled[G * Bsz * AC];

// ---------- fp16 helpers ----------
__device__ __forceinline__ unsigned int f2h2(float lo, float hi) {
    __half2 h = __floats2half2_rn(lo, hi);
    return *reinterpret_cast<unsigned int*>(&h);
}
__device__ __forceinline__ void mma_f16(
    float& d0, float& d1, float& d2, float& d3,
    unsigned int a0, unsigned int a1, unsigned int a2, unsigned int a3,
    unsigned int b0, unsigned int b1)
{
    asm("mma.sync.aligned.m16n8k16.row.col.f32.f16.f16.f32 "
        "{%0,%1,%2,%3}, {%4,%5,%6,%7}, {%8,%9}, {%0,%1,%2,%3};"
        : "+f"(d0), "+f"(d1), "+f"(d2), "+f"(d3)
        : "r"(a0), "r"(a1), "r"(a2), "r"(a3), "r"(b0), "r"(b1));
}

// ============================================================
// Kernel 1 (tensor cores): grouped 3x3 conv + BN + ReLU -> g_h1p (fp16x2)
// Implicit GEMM over K = 9 taps x 16 ci, single fp16.
// grid (k=16, b=2, g=16), 288 threads = 9 warps.
// ============================================================
#define BPITCH 680
#define K1_DYN ((8*BPITCH + 9*128 + 32) * 4)

__global__ __launch_bounds__(288, 2) void k1_tc(
    const float* __restrict__ x,
    const float* __restrict__ W1,
    const float* __restrict__ g1, const float* __restrict__ b1,
    const float* __restrict__ m1, const float* __restrict__ v1)
{
    const int k = blockIdx.x, b = blockIdx.y, g = blockIdx.z;
    extern __shared__ unsigned int dyn[];
    unsigned int* Bv = dyn;                 // 8 ci-pairs x BPITCH (fp16x2)
    unsigned int* Ah = Bv + 8 * BPITCH;     // [tap9][pair8][row16]
    float* scb = reinterpret_cast<float*>(Ah + 9 * 128);

    const int tid = threadIdx.x;

    for (int i = tid; i < 8 * BPITCH; i += 288) Bv[i] = 0u;

    const float* wsrc = W1 + (g * 256 + k * 16) * 144;  // [co16][ci16][tap9]
    for (int i = tid; i < 1152; i += 288) {
        int t = i / 128, rem = i % 128, p = rem / 16, r = rem % 16;
        Ah[i] = f2h2(wsrc[r * 144 + (2 * p) * 9 + t],
                     wsrc[r * 144 + (2 * p + 1) * 9 + t]);
    }
    if (tid < 16) {
        const int ch = g * 256 + k * 16 + tid;
        float sc = g1[ch] * rsqrtf(v1[ch] + EPSV);
        scb[tid] = sc;
        scb[16 + tid] = b1[ch] - m1[ch] * sc;
    }
    __syncthreads();

    const float* xs = x + (b * 256 + k * 16) * 576;
    for (int i = tid; i < 8 * 576; i += 288) {
        int q = i / 576, pos = i % 576;
        int y = pos / 24, xx = pos % 24;
        Bv[q * BPITCH + (y + 1) * 26 + (xx + 1)] =
            f2h2(xs[(2 * q) * 576 + pos], xs[(2 * q + 1) * 576 + pos]);
    }
    __syncthreads();

    const int w    = tid >> 5;
    const int lane = tid & 31;
    const int gq   = lane >> 2;
    const int tg   = lane & 3;

    float d[8][4];
#pragma unroll
    for (int j = 0; j < 8; ++j)
#pragma unroll
        for (int c = 0; c < 4; ++c) d[j][c] = 0.f;

#pragma unroll
    for (int t = 0; t < 9; ++t) {
        const int base = t * 128;
        unsigned int ah0 = Ah[base + tg * 16 + gq];
        unsigned int ah1 = Ah[base + tg * 16 + gq + 8];
        unsigned int ah2 = Ah[base + (tg + 4) * 16 + gq];
        unsigned int ah3 = Ah[base + (tg + 4) * 16 + gq + 8];
        const int ty = t / 3, tx = t % 3;

#pragma unroll
        for (int j = 0; j < 8; ++j) {
            const int nt = w * 8 + j;
            const int y = nt / 3, x0 = (nt % 3) * 8;
            const int pp = (y + ty) * 26 + x0 + gq + tx;
            unsigned int b0 = Bv[tg * BPITCH + pp];
            unsigned int b1 = Bv[(tg + 4) * BPITCH + pp];
            mma_f16(d[j][0], d[j][1], d[j][2], d[j][3], ah0, ah1, ah2, ah3, b0, b1);
        }
    }

    // epilogue: BN + ReLU, pack rows (gq, gq+8) into fp16x2 words
    const float sc0 = scb[gq],     bi0 = scb[16 + gq];
    const float sc1 = scb[gq + 8], bi1 = scb[24 + gq];
    unsigned int* dstp = g_h1p + (((g * 2 + b) * 16 + k) * 8 + gq) * 576;
#pragma unroll
    for (int j = 0; j < 8; ++j) {
        const int nt = w * 8 + j;
        const int pos = nt * 8 + 2 * tg;
        float v0x = fmaxf(fmaf(d[j][0], sc0, bi0), 0.f);
        float v0y = fmaxf(fmaf(d[j][1], sc0, bi0), 0.f);
        float v1x = fmaxf(fmaf(d[j][2], sc1, bi1), 0.f);
        float v1y = fmaxf(fmaf(d[j][3], sc1, bi1), 0.f);
        uint2 pk;
        pk.x = f2h2(v0x, v1x);   // pos:   (row gq, row gq+8)
        pk.y = f2h2(v0y, v1y);   // pos+1
        *reinterpret_cast<uint2*>(dstp + pos) = pk;
    }
}

// ============================================================
// Kernel 2 (tensor cores): per (g,b,k) GEMM + BN + ReLU + avg-pool.
// B tile loaded as packed fp16x2 words (pairing (q, q+8)); A fragments
// use the matching permuted K-order. hsum computed from the same fp16
// values the MMA consumes. Epilogue: relu identity + exact linear part.
// ============================================================
__global__ __launch_bounds__(416, 2) void k2_tc(
    const float* __restrict__ W2,
    const float* __restrict__ g2, const float* __restrict__ b2,
    const float* __restrict__ m2, const float* __restrict__ v2)
{
    const int k = blockIdx.x, b = blockIdx.y, g = blockIdx.z;

    __shared__ unsigned int Bv[8][584];   // pitch 584 (mod 32 == 8)
    __shared__ float part[16][48];
    __shared__ float hsum[16];

    const int tid = threadIdx.x;
    const unsigned int* src = g_h1p + ((g * 2 + b) * 16 + k) * 4608;

    if (tid < 384) {
        const int q = tid / 48, r = tid % 48;
        const unsigned int* sp = src + q * 576;
        float a0 = 0.f, a1 = 0.f;
#pragma unroll
        for (int n = 0; n < 12; ++n) {
            const int pos = r + 48 * n;
            unsigned int wv = sp[pos];
            Bv[q][pos] = wv;
            float2 f = __half22float2(*reinterpret_cast<const __half2*>(&wv));
            a0 += f.x; a1 += f.y;
        }
        part[q][r]     = a0;   // channel q
        part[q + 8][r] = a1;   // channel q+8
    }
    __syncthreads();
    if (tid < 16) {
        float s = 0.f;
#pragma unroll
        for (int j = 0; j < 48; ++j) s += part[tid][j];
        hsum[tid] = s;
    }
    __syncthreads();

    const int w    = tid >> 5;
    const int lane = tid & 31;
    const int gq   = lane >> 2;
    const int tg   = lane & 3;

    const int s0i = w;
    const int s1raw = w + 13;
    const int s1i = (s1raw < 25) ? s1raw : s0i;   // warp 12 duplicates (benign)

    // hsum values for this thread's permuted K slots
    const float hsA = hsum[tg];
    const float hsB = hsum[tg + 8];
    const float hsC = hsum[tg + 4];
    const float hsD = hsum[tg + 12];

    unsigned int ah[2][4];
    float sc[2][2], bi[2][2], bip[2][2], Sd[2][2];
    int acB[2];
    const int ss[2] = { s0i, s1i };
#pragma unroll
    for (int e = 0; e < 2; ++e) {
        acB[e] = k * 400 + ss[e] * 16;
        const int pi0 = g * 6400 + acB[e] + gq;
        const int pi1 = pi0 + 8;
        const float* R0 = W2 + (size_t)pi0 * 16;
        const float* R1 = W2 + (size_t)pi1 * 16;
        // permuted K: slots (2tg,2tg+1) = channels (tg, tg+8);
        //             slots (2tg+8,2tg+9) = channels (tg+4, tg+12)
        float r0a = R0[tg], r0b = R0[tg + 8], r0c = R0[tg + 4], r0d = R0[tg + 12];
        float r1a = R1[tg], r1b = R1[tg + 8], r1c = R1[tg + 4], r1d = R1[tg + 12];
        ah[e][0] = f2h2(r0a, r0b);
        ah[e][1] = f2h2(r1a, r1b);
        ah[e][2] = f2h2(r0c, r0d);
        ah[e][3] = f2h2(r1c, r1d);
        sc[e][0] = g2[pi0] * rsqrtf(v2[pi0] + EPSV);
        bi[e][0] = b2[pi0] - m2[pi0] * sc[e][0];
        sc[e][1] = g2[pi1] * rsqrtf(v2[pi1] + EPSV);
        bi[e][1] = b2[pi1] - m2[pi1] * sc[e][1];
        bip[e][0] = bi[e][0] / sc[e][0];
        bip[e][1] = bi[e][1] / sc[e][1];
        Sd[e][0] = r0a * hsA + r0b * hsB + r0c * hsC + r0d * hsD;
        Sd[e][1] = r1a * hsA + r1b * hsB + r1c * hsC + r1d * hsD;
    }

    float T[2][2] = {{0.f, 0.f}, {0.f, 0.f}};   // Sum |d + bi/sc|

#pragma unroll 4
    for (int nt = 0; nt < 72; ++nt) {
        const int pos = nt * 8 + gq;
        unsigned int b0 = Bv[tg][pos];
        unsigned int b1 = Bv[tg + 4][pos];

#pragma unroll
        for (int e = 0; e < 2; ++e) {
            float d0 = 0.f, d1 = 0.f, d2 = 0.f, d3 = 0.f;
            mma_f16(d0, d1, d2, d3, ah[e][0], ah[e][1], ah[e][2], ah[e][3], b0, b1);
            T[e][0] += fabsf(d0 + bip[e][0]) + fabsf(d1 + bip[e][0]);
            T[e][1] += fabsf(d2 + bip[e][1]) + fabsf(d3 + bip[e][1]);
        }
    }

#pragma unroll
    for (int e = 0; e < 2; ++e) {
        float t0 = T[e][0], t1 = T[e][1];
        float s0 = Sd[e][0], s1 = Sd[e][1];
        t0 += __shfl_xor_sync(0xffffffffu, t0, 1);
        t0 += __shfl_xor_sync(0xffffffffu, t0, 2);
        t1 += __shfl_xor_sync(0xffffffffu, t1, 1);
        t1 += __shfl_xor_sync(0xffffffffu, t1, 2);
        s0 += __shfl_xor_sync(0xffffffffu, s0, 1);
        s0 += __shfl_xor_sync(0xffffffffu, s0, 2);
        s1 += __shfl_xor_sync(0xffffffffu, s1, 1);
        s1 += __shfl_xor_sync(0xffffffffu, s1, 2);
        if (tg == 0) {
            float* dst = g_pooled + (g * 2 + b) * 6400;
            float S0 = fmaf(sc[e][0], s0, 576.f * bi[e][0]);
            float R0 = 0.5f * fmaf(sc[e][0], t0, S0);
            float S1 = fmaf(sc[e][1], s1, 576.f * bi[e][1]);
            float R1 = 0.5f * fmaf(sc[e][1], t1, S1);
            dst[acB[e] + gq]     = (R0 + 100.f * fmaxf(bi[e][0], 0.f)) * (1.f / 676.f);
            dst[acB[e] + gq + 8] = (R1 + 100.f * fmaxf(bi[e][1], 0.f)) * (1.f / 676.f);
        }
    }
}

// ============================================================
// Kernel 4 (fused affinity + output): grid (cgp=8, q=2, i=16),
// 576 threads = 18 warps.
// Phase 1: threads 0..511 compute the 32 affinity dots this block
// needs (p in {0,1} x kk in 0..15), 16 threads per dot, width-16
// shuffle reduce -> smem.
// Phase 2: each thread owns ONE position; 16 independent coalesced
// u32 loads of packed fp16 pairs; 4 scalar stores.
// ============================================================
__global__ __launch_bounds__(576) void k4_out(float* __restrict__ out)
{
    const int cgp = blockIdx.x, q = blockIdx.y, i = blockIdx.z;
    __shared__ float aff[32];   // [p*16 + kk]
    const int tid = threadIdx.x;

    if (tid < 512) {
        const int dd = tid >> 4;        // 0..31 = p*16+kk
        const int t  = tid & 15;
        const int p  = dd >> 4, kk = dd & 15;
        const float* base = g_pooled + (i * 2 + p) * 6400;
        const float* pa = base + i * 400;
        const float* pb = base + kk * 400;
        float s = 0.f;
#pragma unroll 5
        for (int m = t; m < 400; m += 16) s += pa[m] * pb[m];
        s += __shfl_down_sync(0xffffffffu, s, 8, 16);
        s += __shfl_down_sync(0xffffffffu, s, 4, 16);
        s += __shfl_down_sync(0xffffffffu, s, 2, 16);
        s += __shfl_down_sync(0xffffffffu, s, 1, 16);
        if (t == 0) aff[dd] = s * (1.f / 16.f);
    }
    __syncthreads();

    const int pos = tid;   // 0..575
    // word [tile (i*2+q)*16+kk][row cgp][pos]: (lo = ch kk*16+cgp, hi = +8)
    const unsigned int* hb =
        g_h1p + ((size_t)((i * 2 + q) * 16) * 8 + cgp) * 576 + pos;

    float lo0 = 0.f, hi0 = 0.f, lo1 = 0.f, hi1 = 0.f;
#pragma unroll
    for (int kk = 0; kk < 16; ++kk) {
        unsigned int wv = hb[kk * 4608];
        float2 f = __half22float2(*reinterpret_cast<const __half2*>(&wv));
        float w0 = aff[kk], w1 = aff[16 + kk];
        lo0 = fmaf(w0, f.x, lo0); hi0 = fmaf(w0, f.y, hi0);
        lo1 = fmaf(w1, f.x, lo1); hi1 = fmaf(w1, f.y, hi1);
    }
    const int chLo = (i * 2 + q) * 16 + cgp;
    out[(0 * 512 + chLo)     * 576 + pos] = lo0;
    out[(0 * 512 + chLo + 8) * 576 + pos] = hi0;
    out[(1 * 512 + chLo)     * 576 + pos] = lo1;
    out[(1 * 512 + chLo + 8) * 576 + pos] = hi1;
}

// ============================================================
extern "C" void kernel_launch(void* const* d_in, const int* in_sizes, int n_in,
                              void* d_out, int out_size)
{
    const float* x  = (const float*)d_in[0];
    const float* W1 = (const float*)d_in[1];
    const float* g1 = (const float*)d_in[2];
    const float* b1 = (const float*)d_in[3];
    const float* m1 = (const float*)d_in[4];
    const float* v1 = (const float*)d_in[5];
    const float* W2 = (const float*)d_in[6];
    const float* g2 = (const float*)d_in[7];
    const float* b2 = (const float*)d_in[8];
    const float* m2 = (const float*)d_in[9];
    const float* v2 = (const float*)d_in[10];
    float* out = (float*)d_out;

    cudaFuncSetAttribute(k1_tc, cudaFuncAttributeMaxDynamicSharedMemorySize, K1_DYN);

    dim3 grid(16, 2, 16);
    dim3 grid4(8, 2, 16);
    k1_tc <<<grid, 288, K1_DYN>>>(x, W1, g1, b1, m1, v1);
    k2_tc <<<grid, 416>>>(W2, g2, b2, m2, v2);
    k4_out<<<grid4, 576>>>(out);
}